// round 11
// baseline (speedup 1.0000x reference)
#include <cuda_runtime.h>
#include <cstdint>

// out[row, n] = sum_t u[row, t] * K[n, 1023 - t] = sum_j u_rev[row, j] * K[n, j]
// Skinny GEMM 512x64x1024 fp32 via fma.rn.f32x2.
// Block = 8 rows x 32 n, 1024 threads (32 warps, 50% occ). Warp q owns
// j-slice [q*32, q*32+32): warp-private cp.async (2 commit groups of 16 j),
// warp-private reversed-u loads, chunked waits. No block barrier until tail.

#define T_LEN   1024
#define N_ORD   64
#define RPB     8
#define NPB     32
#define KP      1028         // pitch % 32 == 4 -> conflict-free LDS.128 phases
#define THREADS 1024
#define NBLOCKS 128
#define RED_P   9            // tail reduction pitch (coprime with 32 banks)

__device__ __forceinline__ void cp_async16(void* dst, const void* src) {
    unsigned s = (unsigned)__cvta_generic_to_shared(dst);
    asm volatile("cp.async.cg.shared.global [%0], [%1], 16;\n"
                 :: "r"(s), "l"(src) : "memory");
}
__device__ __forceinline__ void cp_commit() {
    asm volatile("cp.async.commit_group;\n" ::: "memory");
}
template <int N>
__device__ __forceinline__ void cp_wait() {
    asm volatile("cp.async.wait_group %0;\n" :: "n"(N) : "memory");
}
// d += a * b, packed 2xf32 (sm_103a only; ptxas never emits from C++)
__device__ __forceinline__ void ffma2(unsigned long long& d,
                                      unsigned long long a,
                                      unsigned long long b) {
    asm("fma.rn.f32x2 %0, %1, %2, %0;" : "+l"(d) : "l"(a), "l"(b));
}

extern __shared__ float smem[];
// layout: u_rev[8*1024] | K[32*KP]  = (8192 + 32896)*4 = 164352 bytes
// tail reduction reuses the K region (needs 1024*RED_P floats = 36864B).

__global__ void __launch_bounds__(THREADS, 1)
hippo_last_kernel(const float* __restrict__ U,
                  const float* __restrict__ K,
                  float* __restrict__ out)
{
    float* u_s = smem;                    // time-reversed u
    float* k_s = smem + RPB * T_LEN;

    const int tid  = threadIdx.x;
    const int lane = tid & 31;            // = n within block (mainloop role)
    const int q    = tid >> 5;            // 0..31 : warp owns j-slice [q*32, +32)
    const int jb0  = q * 32;

    const int rg = blockIdx.x >> 1;       // row group (8 rows)
    const int h  = blockIdx.x & 1;        // n half
    const float* Ublk = U + (size_t)rg * RPB * T_LEN;
    const float* Kblk = K + (size_t)h * NPB * T_LEN;

    // ---- K: warp-private cp.async, 2 commit groups (16 j-columns each) ----
    #pragma unroll
    for (int c = 0; c < 2; ++c) {
        #pragma unroll
        for (int w = 0; w < 4; ++w) {
            int idx = lane + 32 * w;      // 0..127
            int nn  = idx >> 2;           // K row 0..31
            int v   = idx & 3;            // float4 within 16-float subchunk
            int j   = jb0 + c * 16 + v * 4;
            cp_async16(&k_s[nn * KP + j], &Kblk[nn * T_LEN + j]);
        }
        cp_commit();
    }

    // ---- u: warp-private slice (8 rows x 32 j), loaded reversed ----
    #pragma unroll
    for (int w = 0; w < 2; ++w) {
        int idx = lane + 32 * w;          // 0..63
        int r   = idx >> 3;               // row 0..7
        int jv  = idx & 7;                // float4 within 32-float j-slice
        int j   = jb0 + jv * 4;
        float4 a = *(const float4*)&Ublk[r * T_LEN + (T_LEN - 4) - j];
        *(float4*)&u_s[r * T_LEN + j] = make_float4(a.w, a.z, a.y, a.x);
    }
    __syncwarp();                          // u visible across lanes

    // ---- warp-private mainloop: 2 chunks x 4 its ----
    unsigned long long acc[RPB];
    #pragma unroll
    for (int r = 0; r < RPB; ++r) acc[r] = 0ull;

    const float* kp = k_s + lane * KP;    // lane = n

    #pragma unroll
    for (int c = 0; c < 2; ++c) {
        if (c == 0) cp_wait<1>(); else cp_wait<0>();
        __syncwarp();                      // K chunk c visible across lanes

        #pragma unroll
        for (int it = 0; it < 4; ++it) {
            const int s = jb0 + c * 16 + it * 4;
            ulonglong2 k2 = *(const ulonglong2*)&kp[s];
            #pragma unroll
            for (int r = 0; r < RPB; ++r) {
                ulonglong2 a2 = *(const ulonglong2*)&u_s[r * T_LEN + s];
                ffma2(acc[r], a2.x, k2.x);
                ffma2(acc[r], a2.y, k2.y);
            }
        }
    }

    // ---- fold packed halves ----
    float vr[RPB];
    #pragma unroll
    for (int r = 0; r < RPB; ++r) {
        float2 f = *(float2*)&acc[r];
        vr[r] = f.x + f.y;
    }

    // ---- cross-warp reduction in k_s, pitch 9 (conflict-free gather) ----
    __syncthreads();                       // all mainloop smem reads done
    float* red = k_s;                      // 1024 * 9 floats = 36864 B
    #pragma unroll
    for (int r = 0; r < RPB; ++r)
        red[tid * RED_P + r] = vr[r];
    __syncthreads();

    if (tid < RPB * NPB) {                 // 256 outputs
        const int r_out = tid >> 5;        // 0..7
        const int n_out = tid & 31;
        float v = 0.f;
        #pragma unroll
        for (int qq = 0; qq < 32; ++qq)
            v += red[(qq * 32 + n_out) * RED_P + r_out];
        out[(size_t)(rg * RPB + r_out) * N_ORD + h * NPB + n_out] = v;
    }
}

extern "C" void kernel_launch(void* const* d_in, const int* in_sizes, int n_in,
                              void* d_out, int out_size)
{
    (void)in_sizes; (void)n_in; (void)out_size;
    const float* U   = (const float*)d_in[0];  // (4,2,64,1024) f32
    const float* K   = (const float*)d_in[1];  // (64,1024) f32
    float*       out = (float*)d_out;          // (4,2,64,64) f32

    const size_t SMEM = (RPB * T_LEN + NPB * KP) * sizeof(float); // 164352
    cudaFuncSetAttribute(hippo_last_kernel,
                         cudaFuncAttributeMaxDynamicSharedMemorySize, (int)SMEM);

    hippo_last_kernel<<<NBLOCKS, THREADS, SMEM>>>(U, K, out);
}

// round 17
// speedup vs baseline: 1.3488x; 1.3488x over previous
#include <cuda_runtime.h>
#include <cstdint>

// out[row, n] = sum_t u[row, t] * K[n, 1023 - t] = sum_j u[row, 1023-j] * K[n, j]
// Skinny GEMM 512x64x1024 fp32. NO smem staging: lane = j makes K and
// (reversed) u reads perfectly coalesced LDG.128 straight from gmem; the
// 160KB working set is L1-resident and shared across warps. fma.rn.f32x2
// accumulators; butterfly lane-reduction; tiny static-smem combine for the
// j-half split. No cp.async, no mbarrier, no dynamic smem -> nothing can hang.
//
// Block = 8 rows x 32 n (grid 128). 32 warps = (p: n-quad, rh: row-half,
// jh: j-half). Per lane-iter: 4 K-LDG.128 + 4 u-LDG.128 -> 32 ffma2.

#define T_LEN   1024
#define N_ORD   64
#define THREADS 1024
#define NBLOCKS 128

// d += a * b, packed 2xf32 (sm_103a only; ptxas never emits from C++)
__device__ __forceinline__ void ffma2(unsigned long long& d,
                                      unsigned long long a,
                                      unsigned long long b) {
    asm("fma.rn.f32x2 %0, %1, %2, %0;" : "+l"(d) : "l"(a), "l"(b));
}
__device__ __forceinline__ unsigned long long packf2(float lo, float hi) {
    unsigned long long r;
    asm("mov.b64 %0, {%1, %2};" : "=l"(r) : "f"(lo), "f"(hi));
    return r;
}

__global__ void __launch_bounds__(THREADS, 1)
hippo_last_kernel(const float* __restrict__ U,
                  const float* __restrict__ K,
                  float* __restrict__ out)
{
    __shared__ float red[32][17];          // [warp][nn*4+r], padded

    const int tid  = threadIdx.x;
    const int lane = tid & 31;
    const int w    = tid >> 5;             // 0..31
    const int p    = w >> 2;               // n-quad: n = 4p..4p+3 (within half)
    const int rh   = (w >> 1) & 1;         // row half: rows 4rh..4rh+3
    const int jh   = w & 1;                // j half: j in [jh*512, jh*512+512)

    const int rg = blockIdx.x >> 1;        // row group (8 rows)
    const int h  = blockIdx.x & 1;         // n half

    // Base pointers; per-iter offsets are compile-time immediates after unroll.
    const float* kbase = K + (size_t)h * 32 * T_LEN + (size_t)(4 * p) * T_LEN
                           + jh * 512 + lane * 4;
    const float* ubase = U + (size_t)rg * 8 * T_LEN + (size_t)(4 * rh) * T_LEN
                           + (T_LEN - 4) - jh * 512 - lane * 4;

    unsigned long long acc[16];            // acc[nn*4 + r]
    #pragma unroll
    for (int i = 0; i < 16; ++i) acc[i] = 0ull;

    #pragma unroll
    for (int it = 0; it < 4; ++it) {
        const int ko =  it * 128;          // k offset (floats), immediate
        const int uo = -it * 128;          // u offset (floats), immediate

        // 4 K rows, this lane's float4 of j (coalesced across lanes)
        unsigned long long klo[4], khi[4];
        #pragma unroll
        for (int nn = 0; nn < 4; ++nn) {
            float4 k4 = *(const float4*)&kbase[nn * T_LEN + ko];
            // u at (1020-j0) holds u_rev[j0+3..j0] -> pair (x,y)<->( k.w,k.z ),
            // (z,w)<->(k.y,k.x)
            klo[nn] = packf2(k4.w, k4.z);
            khi[nn] = packf2(k4.y, k4.x);
        }
        #pragma unroll
        for (int r = 0; r < 4; ++r) {
            ulonglong2 uu = *(const ulonglong2*)&ubase[r * T_LEN + uo];
            #pragma unroll
            for (int nn = 0; nn < 4; ++nn) {
                ffma2(acc[nn * 4 + r], uu.x, klo[nn]);
                ffma2(acc[nn * 4 + r], uu.y, khi[nn]);
            }
        }
    }

    // ---- fold packed halves, butterfly-reduce over lanes (j within half) ----
    float v[16];
    #pragma unroll
    for (int i = 0; i < 16; ++i) {
        float2 f = *(float2*)&acc[i];
        v[i] = f.x + f.y;
    }
    #pragma unroll
    for (int off = 16; off >= 1; off >>= 1) {
        #pragma unroll
        for (int i = 0; i < 16; ++i)
            v[i] += __shfl_xor_sync(0xFFFFFFFFu, v[i], off);
    }

    if (lane == 0) {
        #pragma unroll
        for (int i = 0; i < 16; ++i) red[w][i] = v[i];
    }
    __syncthreads();

    // ---- combine jh halves, write 256 outputs ----
    if (tid < 256) {
        const int n_out = tid & 31;        // within half
        const int r_out = tid >> 5;        // 0..7
        const int pp  = n_out >> 2;
        const int nn  = n_out & 3;
        const int rrh = r_out >> 2;
        const int rr  = r_out & 3;
        const int w0  = pp * 4 + rrh * 2;  // jh = 0
        const int idx = nn * 4 + rr;
        float val = red[w0][idx] + red[w0 + 1][idx];
        out[(size_t)(rg * 8 + r_out) * N_ORD + h * 32 + n_out] = val;
    }
}

extern "C" void kernel_launch(void* const* d_in, const int* in_sizes, int n_in,
                              void* d_out, int out_size)
{
    (void)in_sizes; (void)n_in; (void)out_size;
    const float* U   = (const float*)d_in[0];  // (4,2,64,1024) f32
    const float* K   = (const float*)d_in[1];  // (64,1024) f32
    float*       out = (float*)d_out;          // (4,2,64,64) f32

    hippo_last_kernel<<<NBLOCKS, THREADS>>>(U, K, out);
}